// round 15
// baseline (speedup 1.0000x reference)
#include <cuda_runtime.h>
#include <cuda_bf16.h>
#include <math.h>
#include <stdint.h>

// Problem constants
#define BB 2
#define HH 8
#define TT 4096
#define DD 64
#define CC 512
#define MM (BB*TT)   // 8192

// Scratch (device globals: allocation-free)
__device__ float g_q[BB*HH*TT*DD];   // [b,h,t,d]  (tf32-rounded fp32)
__device__ float g_k[BB*HH*TT*DD];
__device__ float g_v[BB*HH*TT*DD];

// Pre-split bf16 hi/lo planes (stored as bf16x2 in uint32)
__device__ uint32_t g_xh[MM*CC/2], g_xl[MM*CC/2];       // x
__device__ uint32_t g_wh[4*CC*CC/2], g_wl[4*CC*CC/2];   // Wq,Wk,Wv,Wout
__device__ uint32_t g_yh[MM*CC/2], g_yl[MM*CC/2];       // attention output

// ---------------------------------------------------------------------------
// Helpers
// ---------------------------------------------------------------------------

__device__ __forceinline__ uint32_t f2tf(float f) {
    uint32_t u;
    asm("cvt.rna.tf32.f32 %0, %1;" : "=r"(u) : "f"(f));
    return u;
}
__device__ __forceinline__ float ex2(float x) {
    float y;
    asm("ex2.approx.ftz.f32 %0, %1;" : "=f"(y) : "f"(x));
    return y;
}
__device__ __forceinline__ void mma_tf32(float c[4],
                                         uint32_t a0, uint32_t a1, uint32_t a2, uint32_t a3,
                                         uint32_t b0, uint32_t b1) {
    asm volatile(
        "mma.sync.aligned.m16n8k8.row.col.f32.tf32.tf32.f32 "
        "{%0,%1,%2,%3}, {%4,%5,%6,%7}, {%8,%9}, {%0,%1,%2,%3};"
        : "+f"(c[0]), "+f"(c[1]), "+f"(c[2]), "+f"(c[3])
        : "r"(a0), "r"(a1), "r"(a2), "r"(a3), "r"(b0), "r"(b1));
}
__device__ __forceinline__ void mma_bf16(float c[4],
                                         uint32_t a0, uint32_t a1, uint32_t a2, uint32_t a3,
                                         uint32_t b0, uint32_t b1) {
    asm volatile(
        "mma.sync.aligned.m16n8k16.row.col.f32.bf16.bf16.f32 "
        "{%0,%1,%2,%3}, {%4,%5,%6,%7}, {%8,%9}, {%0,%1,%2,%3};"
        : "+f"(c[0]), "+f"(c[1]), "+f"(c[2]), "+f"(c[3])
        : "r"(a0), "r"(a1), "r"(a2), "r"(a3), "r"(b0), "r"(b1));
}

// bf16 hi/lo split of a float pair; hi+lo captures ~16 mantissa bits.
__device__ __forceinline__ void split2_bf16(float x, float y, uint32_t& hi, uint32_t& lo) {
    __nv_bfloat162 h = __floats2bfloat162_rn(x, y);
    float rx = x - __bfloat162float(h.x);
    float ry = y - __bfloat162float(h.y);
    __nv_bfloat162 l = __floats2bfloat162_rn(rx, ry);
    hi = *(uint32_t*)&h;
    lo = *(uint32_t*)&l;
}

__device__ __forceinline__ void cp16(uint32_t saddr, const void* gptr) {
    asm volatile("cp.async.cg.shared.global [%0], [%1], 16;"
                 :: "r"(saddr), "l"(gptr));
}
__device__ __forceinline__ void cp_commit() {
    asm volatile("cp.async.commit_group;");
}
__device__ __forceinline__ void cp_wait1() {
    asm volatile("cp.async.wait_group 1;");
}
__device__ __forceinline__ void cp_wait0() {
    asm volatile("cp.async.wait_group 0;");
}

// ---------------------------------------------------------------------------
// Pre-split: x and the four W matrices -> bf16 hi/lo planes in gmem.
// ---------------------------------------------------------------------------

#define XN4 (MM*CC/4)   // float4 count in x
#define WN4 (CC*CC/4)   // float4 count per W

__global__ __launch_bounds__(256) void split_inputs(const float* __restrict__ x,
                                                    const float* __restrict__ Wq,
                                                    const float* __restrict__ Wk,
                                                    const float* __restrict__ Wv,
                                                    const float* __restrict__ Wo)
{
    int i = blockIdx.x * 256 + threadIdx.x;
    const float* src;
    uint32_t *dh, *dl;
    int off;
    if (i < XN4) {
        src = x; dh = g_xh; dl = g_xl; off = i;
    } else {
        int j = i - XN4;
        int w = j / WN4;
        off = j - w * WN4;
        src = (w == 0) ? Wq : (w == 1) ? Wk : (w == 2) ? Wv : Wo;
        dh = g_wh + w * (CC * CC / 2);
        dl = g_wl + w * (CC * CC / 2);
    }
    float4 v = ((const float4*)src)[off];
    uint32_t h0, l0, h1, l1;
    split2_bf16(v.x, v.y, h0, l0);
    split2_bf16(v.z, v.w, h1, l1);
    ((uint2*)dh)[off] = make_uint2(h0, h1);
    ((uint2*)dl)[off] = make_uint2(l0, l1);
}

// ---------------------------------------------------------------------------
// Tensor-core split-bf16 GEMM, pre-split inputs, cp.async 2-stage (unchanged).
// ---------------------------------------------------------------------------

#define GSTR 20
#define GPLANE (128 * GSTR)                        // u32 per plane
#define GSTAGE4 (4 * GPLANE)                       // u32 per stage
#define GEMM_SMEM (2 * GSTAGE4 * (int)sizeof(uint32_t))   // 81920 B

__device__ __forceinline__ void g_issue(uint32_t sbase,
                                        const uint32_t* __restrict__ Ah_g,
                                        const uint32_t* __restrict__ Al_g,
                                        const uint32_t* __restrict__ Bh_g,
                                        const uint32_t* __restrict__ Bl_g,
                                        int k0u)   // u32 col offset = k0/2
{
    const int tid = threadIdx.x;
#pragma unroll
    for (int i = 0; i < 8; i++) {
        int c = i * 256 + tid;          // 0..2047
        int plane = c >> 9;             // 512 chunks per plane
        int row = (c >> 2) & 127;
        int ch  = c & 3;                // 16B chunk within row
        const uint32_t* g = (plane == 0) ? Ah_g : (plane == 1) ? Al_g
                          : (plane == 2) ? Bh_g : Bl_g;
        uint32_t dst = sbase + (plane * GPLANE + row * GSTR + ch * 4) * 4;
        cp16(dst, g + (size_t)row * (CC / 2) + k0u + ch * 4);
    }
}

__device__ __forceinline__ void gemm_mainloop(const uint32_t* __restrict__ Ah_g,
                                              const uint32_t* __restrict__ Al_g,
                                              const uint32_t* __restrict__ Bh_g,
                                              const uint32_t* __restrict__ Bl_g,
                                              uint32_t* smu,
                                              float acc[2][8][4])
{
    const int tid  = threadIdx.x;
    const int w    = tid >> 5;
    const int lane = tid & 31;
    const int g    = lane >> 2;
    const int t    = lane & 3;
    const int wm   = w >> 1;
    const int wn   = w & 1;

    const uint32_t sm_u32 = (uint32_t)__cvta_generic_to_shared(smu);

#pragma unroll
    for (int mt = 0; mt < 2; mt++)
#pragma unroll
        for (int nt = 0; nt < 8; nt++)
#pragma unroll
            for (int k = 0; k < 4; k++) acc[mt][nt][k] = 0.f;

    g_issue(sm_u32, Ah_g, Al_g, Bh_g, Bl_g, 0);
    cp_commit();

    const int NITER = CC / 32;          // 16
    for (int it = 0; it < NITER; it++) {
        if (it + 1 < NITER) {
            g_issue(sm_u32 + (((it + 1) & 1) * GSTAGE4) * 4,
                    Ah_g, Al_g, Bh_g, Bl_g, (it + 1) * 16);
            cp_commit();
            cp_wait1();
        } else {
            cp_wait0();
        }
        __syncthreads();

        const uint32_t* stage = smu + (it & 1) * GSTAGE4;
        const uint32_t* Ah = stage;
        const uint32_t* Al = stage + GPLANE;
        const uint32_t* Bh = stage + 2 * GPLANE;
        const uint32_t* Bl = stage + 3 * GPLANE;

#pragma unroll
        for (int ks = 0; ks < 2; ks++) {
            const int kb = ks * 8;
            uint32_t ah[2][4], al[2][4], b[8][2];
#pragma unroll
            for (int mt = 0; mt < 2; mt++) {
                int r = wm * 32 + mt * 16 + g;
                ah[mt][0] = Ah[(r)     * GSTR + kb + t];
                ah[mt][1] = Ah[(r + 8) * GSTR + kb + t];
                ah[mt][2] = Ah[(r)     * GSTR + kb + t + 4];
                ah[mt][3] = Ah[(r + 8) * GSTR + kb + t + 4];
                al[mt][0] = Al[(r)     * GSTR + kb + t];
                al[mt][1] = Al[(r + 8) * GSTR + kb + t];
                al[mt][2] = Al[(r)     * GSTR + kb + t + 4];
                al[mt][3] = Al[(r + 8) * GSTR + kb + t + 4];
            }
#pragma unroll
            for (int nt = 0; nt < 8; nt++) {
                int cn = wn * 64 + nt * 8 + g;
                b[nt][0] = Bh[cn * GSTR + kb + t];
                b[nt][1] = Bh[cn * GSTR + kb + t + 4];
            }
#pragma unroll
            for (int nt = 0; nt < 8; nt++)
#pragma unroll
                for (int mt = 0; mt < 2; mt++)
                    mma_bf16(acc[mt][nt], ah[mt][0], ah[mt][1], ah[mt][2], ah[mt][3],
                             b[nt][0], b[nt][1]);
#pragma unroll
            for (int nt = 0; nt < 8; nt++)
#pragma unroll
                for (int mt = 0; mt < 2; mt++)
                    mma_bf16(acc[mt][nt], al[mt][0], al[mt][1], al[mt][2], al[mt][3],
                             b[nt][0], b[nt][1]);
#pragma unroll
            for (int nt = 0; nt < 8; nt++) {
                int cn = wn * 64 + nt * 8 + g;
                b[nt][0] = Bl[cn * GSTR + kb + t];
                b[nt][1] = Bl[cn * GSTR + kb + t + 4];
            }
#pragma unroll
            for (int nt = 0; nt < 8; nt++)
#pragma unroll
                for (int mt = 0; mt < 2; mt++)
                    mma_bf16(acc[mt][nt], ah[mt][0], ah[mt][1], ah[mt][2], ah[mt][3],
                             b[nt][0], b[nt][1]);
        }
        __syncthreads();
    }
}

// QKV projections: epilogue rounds to tf32 and scatters into [b,h,t,d].
__global__ __launch_bounds__(256, 2) void gemm_qkv_tc()
{
    const int z = blockIdx.z;
    float* Out = (z == 0) ? g_q : (z == 1) ? g_k : g_v;

    extern __shared__ uint32_t smu[];
    const int m0 = blockIdx.y * 128, n0 = blockIdx.x * 128;

    float acc[2][8][4];
    gemm_mainloop(g_xh + (size_t)m0 * (CC / 2),
                  g_xl + (size_t)m0 * (CC / 2),
                  g_wh + (size_t)z * (CC * CC / 2) + (size_t)n0 * (CC / 2),
                  g_wl + (size_t)z * (CC * CC / 2) + (size_t)n0 * (CC / 2),
                  smu, acc);

    const int lane = threadIdx.x & 31;
    const int w    = threadIdx.x >> 5;
    const int g = lane >> 2, t = lane & 3;
    const int wm = w >> 1, wn = w & 1;

#pragma unroll
    for (int mt = 0; mt < 2; mt++) {
        int row = m0 + wm * 32 + mt * 16 + g;
        int b_  = row >> 12;
        int tr  = row & 4095;
#pragma unroll
        for (int nt = 0; nt < 8; nt++) {
            int col = n0 + wn * 64 + nt * 8 + 2 * t;
            int h = col >> 6, d = col & 63;
            float* base = Out + (((size_t)(b_ * HH + h) * TT) + tr) * DD + d;
            *(float2*)base = make_float2(__uint_as_float(f2tf(acc[mt][nt][0])),
                                         __uint_as_float(f2tf(acc[mt][nt][1])));
            *(float2*)(base + 8 * DD) =
                          make_float2(__uint_as_float(f2tf(acc[mt][nt][2])),
                                      __uint_as_float(f2tf(acc[mt][nt][3])));
        }
    }
}

// Output projection: A = pre-split y planes, B = Wout plane; fp32 epilogue.
__global__ __launch_bounds__(256, 2) void gemm_out_tc(float* __restrict__ OutP)
{
    extern __shared__ uint32_t smu[];
    const int m0 = blockIdx.y * 128, n0 = blockIdx.x * 128;

    float acc[2][8][4];
    gemm_mainloop(g_yh + (size_t)m0 * (CC / 2),
                  g_yl + (size_t)m0 * (CC / 2),
                  g_wh + 3 * (size_t)(CC * CC / 2) + (size_t)n0 * (CC / 2),
                  g_wl + 3 * (size_t)(CC * CC / 2) + (size_t)n0 * (CC / 2),
                  smu, acc);

    const int lane = threadIdx.x & 31;
    const int w    = threadIdx.x >> 5;
    const int g = lane >> 2, t = lane & 3;
    const int wm = w >> 1, wn = w & 1;

#pragma unroll
    for (int mt = 0; mt < 2; mt++) {
        int row = m0 + wm * 32 + mt * 16 + g;
#pragma unroll
        for (int nt = 0; nt < 8; nt++) {
            int col = n0 + wn * 64 + nt * 8 + 2 * t;
            float* base = OutP + (size_t)row * CC + col;
            *(float2*)base            = make_float2(acc[mt][nt][0], acc[mt][nt][1]);
            *(float2*)(base + 8 * CC) = make_float2(acc[mt][nt][2], acc[mt][nt][3]);
        }
    }
}

// ---------------------------------------------------------------------------
// Tensor-core flash attention (tf32 mma.sync m16n8k8), fixed-max softmax.
// 4 warps, 128-query tile, 32 rows/warp (mt=2), 64-key tiles, cp.async
// pipelined K/V.
// NEW vs R13:
//  - Q fragments hoisted into registers (Q invariant across key tiles):
//    zero Q LDS in the main loop.
//  - Fixed-max softmax fused into the QK nt-loop (no row max needed), so
//    only 16 score registers are live at a time (was 64).
//  - Q smem staging ALIASES the Ps slab (Q staged once, before first Ps
//    write; barrier-ordered). Smem 105.5KB -> 70.7KB => 3 CTAs/SM.
// ---------------------------------------------------------------------------

#define KSTR 68
#define VSTR 72
// R1 = Q-stage/Ps : 128 x KSTR ; K : 64 x KSTR ; V : 64 x VSTR
#define FLASH_SMEM ((128*KSTR + 64*KSTR + 64*VSTR) * (int)sizeof(uint32_t)) // 70656
#define MBIAS 16.0f

__global__ __launch_bounds__(128, 3) void flash_tc()
{
    const int bh    = blockIdx.y;
    const int qtile = gridDim.x - 1 - blockIdx.x;   // long tiles launch first
    const int q0    = qtile * 128;

    const float* Qg = g_q + (size_t)bh * TT * DD;
    const float* Kg = g_k + (size_t)bh * TT * DD;
    const float* Vg = g_v + (size_t)bh * TT * DD;

    extern __shared__ uint32_t smu[];
    uint32_t* Ps = smu;                    // 128 x KSTR (also Q staging)
    uint32_t* Ks = Ps + 128 * KSTR;        // 64 x KSTR
    uint32_t* Vs = Ks + 64 * KSTR;         // 64 x VSTR
    const uint32_t Ks_s = (uint32_t)__cvta_generic_to_shared(Ks);
    const uint32_t Vs_s = (uint32_t)__cvta_generic_to_shared(Vs);

    const int tid  = threadIdx.x;
    const int w    = tid >> 5;             // warp 0..3 -> rows w*32..w*32+31
    const int lane = tid & 31;
    const int g    = lane >> 2;
    const int t    = lane & 3;

    const int ntiles = 2 * qtile + 2;

    auto issueK = [&](int j0) {
#pragma unroll
        for (int i = 0; i < 8; i++) {
            int c = i * 128 + tid;
            int row = c >> 4, ch = c & 15;
            cp16(Ks_s + (row * KSTR + ch * 4) * 4, Kg + (size_t)(j0 + row) * DD + ch * 4);
        }
    };
    auto issueV = [&](int j0) {
#pragma unroll
        for (int i = 0; i < 8; i++) {
            int c = i * 128 + tid;
            int row = c >> 4, ch = c & 15;
            cp16(Vs_s + (row * VSTR + ch * 4) * 4, Vg + (size_t)(j0 + row) * DD + ch * 4);
        }
    };

    issueK(0); cp_commit();
    issueV(0); cp_commit();

    // Stage Q tile into the Ps slab (coalesced), then lift fragments into
    // registers. Ps is only written after the tile-0 __syncthreads, which
    // orders it against every warp's fragment loads.
    for (int i = tid; i < 2048; i += 128) {
        int r = i >> 4, c4 = (i & 15) * 4;
        *(float4*)&Ps[r * KSTR + c4] = *(const float4*)(Qg + (size_t)(q0 + r) * DD + c4);
    }
    __syncthreads();

    uint32_t qf[2][8][4];
#pragma unroll
    for (int mt = 0; mt < 2; mt++) {
        const int r = w * 32 + mt * 16 + g;
#pragma unroll
        for (int ks = 0; ks < 8; ks++) {
            qf[mt][ks][0] = Ps[(r)     * KSTR + ks * 8 + t];
            qf[mt][ks][1] = Ps[(r + 8) * KSTR + ks * 8 + t];
            qf[mt][ks][2] = Ps[(r)     * KSTR + ks * 8 + t + 4];
            qf[mt][ks][3] = Ps[(r + 8) * KSTR + ks * 8 + t + 4];
        }
    }

    float l[4];                            // [mt*2 + half]
#pragma unroll
    for (int i = 0; i < 4; i++) l[i] = 0.f;
    float o[2][8][4];
#pragma unroll
    for (int mt = 0; mt < 2; mt++)
#pragma unroll
        for (int dt = 0; dt < 8; dt++)
#pragma unroll
            for (int k = 0; k < 4; k++) o[mt][dt][k] = 0.f;

    const float SC = 0.125f * 1.4426950408889634f;   // 1/sqrt(64) * log2(e)
    const int rA0 = w * 32 + g;            // mt=0 row; mt=1 adds 16

    for (int jt = 0; jt < ntiles; jt++) {
        const int j0 = jt * 64;

        cp_wait1();           // K(jt) ready (V(jt) pending)
        __syncthreads();      // K visible; prior-iter Ps readers done

        const bool diag = (jt >= 2 * qtile);

        // ---- fused S = Q K^T + fixed-max softmax, per nt-pair
#pragma unroll
        for (int ntp = 0; ntp < 4; ntp++) {
            float c[2][2][4];
#pragma unroll
            for (int mt = 0; mt < 2; mt++)
#pragma unroll
                for (int q2 = 0; q2 < 2; q2++)
#pragma unroll
                    for (int k = 0; k < 4; k++) c[mt][q2][k] = 0.f;

#pragma unroll
            for (int ks = 0; ks < 8; ks++) {
                uint32_t b00 = Ks[((2 * ntp)     * 8 + g) * KSTR + ks * 8 + t];
                uint32_t b01 = Ks[((2 * ntp)     * 8 + g) * KSTR + ks * 8 + t + 4];
                uint32_t b10 = Ks[((2 * ntp + 1) * 8 + g) * KSTR + ks * 8 + t];
                uint32_t b11 = Ks[((2 * ntp + 1) * 8 + g) * KSTR + ks * 8 + t + 4];
#pragma unroll
                for (int mt = 0; mt < 2; mt++) {
                    mma_tf32(c[mt][0], qf[mt][ks][0], qf[mt][ks][1],
                             qf[mt][ks][2], qf[mt][ks][3], b00, b01);
                    mma_tf32(c[mt][1], qf[mt][ks][0], qf[mt][ks][1],
                             qf[mt][ks][2], qf[mt][ks][3], b10, b11);
                }
            }

#pragma unroll
            for (int q2 = 0; q2 < 2; q2++) {
                const int nt = 2 * ntp + q2;
                const int j  = j0 + nt * 8 + 2 * t;
#pragma unroll
                for (int mt = 0; mt < 2; mt++) {
                    const int rowA = rA0 + mt * 16;
                    const int qA   = q0 + rowA;
                    float s0 = c[mt][q2][0] * SC - MBIAS;
                    float s1 = c[mt][q2][1] * SC - MBIAS;
                    float s2 = c[mt][q2][2] * SC - MBIAS;
                    float s3 = c[mt][q2][3] * SC - MBIAS;
                    if (diag) {
                        if (j     > qA)     s0 = -1e30f;
                        if (j + 1 > qA)     s1 = -1e30f;
                        if (j     > qA + 8) s2 = -1e30f;
                        if (j + 1 > qA + 8) s3 = -1e30f;
                    }
                    float p0 = ex2(s0), p1 = ex2(s1);
                    float p2 = ex2(s2), p3 = ex2(s3);
                    l[2 * mt]     += p0 + p1;
                    l[2 * mt + 1] += p2 + p3;
                    *(uint2*)&Ps[(rowA)     * KSTR + nt * 8 + 2 * t] =
                        make_uint2(f2tf(p0), f2tf(p1));
                    *(uint2*)&Ps[(rowA + 8) * KSTR + nt * 8 + 2 * t] =
                        make_uint2(f2tf(p2), f2tf(p3));
                }
            }
        }

        // Ks readers done -> prefetch next K during PV
        __syncthreads();
        if (jt + 1 < ntiles) issueK(j0 + 64);
        cp_commit();

        cp_wait1();           // V(jt) ready (K(jt+1) pending)
        __syncthreads();      // V visible (Ps rows are warp-private)

        // ---- O += P V
#pragma unroll
        for (int kt = 0; kt < 8; kt++) {
            uint32_t a[2][4];
#pragma unroll
            for (int mt = 0; mt < 2; mt++) {
                int r = rA0 + mt * 16;
                a[mt][0] = Ps[(r)     * KSTR + kt * 8 + t];
                a[mt][1] = Ps[(r + 8) * KSTR + kt * 8 + t];
                a[mt][2] = Ps[(r)     * KSTR + kt * 8 + t + 4];
                a[mt][3] = Ps[(r + 8) * KSTR + kt * 8 + t + 4];
            }
#pragma unroll
            for (int dt = 0; dt < 8; dt++) {
                uint32_t b0 = Vs[(kt * 8 + t)     * VSTR + dt * 8 + g];
                uint32_t b1 = Vs[(kt * 8 + t + 4) * VSTR + dt * 8 + g];
#pragma unroll
                for (int mt = 0; mt < 2; mt++)
                    mma_tf32(o[mt][dt], a[mt][0], a[mt][1], a[mt][2], a[mt][3], b0, b1);
            }
        }

        // Vs readers done -> prefetch next V during next QK
        __syncthreads();
        if (jt + 1 < ntiles) issueV(j0 + 64);
        cp_commit();
    }

    // ---- normalize + write y as pre-split bf16 hi/lo planes
    const int h  = bh & 7;
    const int b_ = bh >> 3;
#pragma unroll
    for (int mt = 0; mt < 2; mt++) {
        float lA = l[2 * mt];
        lA += __shfl_xor_sync(0xffffffffu, lA, 1);
        lA += __shfl_xor_sync(0xffffffffu, lA, 2);
        float lB = l[2 * mt + 1];
        lB += __shfl_xor_sync(0xffffffffu, lB, 1);
        lB += __shfl_xor_sync(0xffffffffu, lB, 2);
        const float iA = 1.f / lA, iB = 1.f / lB;

        const int qA = q0 + rA0 + mt * 16;
        size_t baseA = ((size_t)(b_ * TT + qA))     * CC + h * 64;
        size_t baseB = ((size_t)(b_ * TT + qA + 8)) * CC + h * 64;
#pragma unroll
        for (int dt = 0; dt < 8; dt++) {
            uint32_t hh, ll;
            split2_bf16(o[mt][dt][0] * iA, o[mt][dt][1] * iA, hh, ll);
            size_t ia = (baseA + dt * 8 + 2 * t) >> 1;
            g_yh[ia] = hh; g_yl[ia] = ll;
            split2_bf16(o[mt][dt][2] * iB, o[mt][dt][3] * iB, hh, ll);
            size_t ib = (baseB + dt * 8 + 2 * t) >> 1;
            g_yh[ib] = hh; g_yl[ib] = ll;
        }
    }
}

// ---------------------------------------------------------------------------

extern "C" void kernel_launch(void* const* d_in, const int* in_sizes, int n_in,
                              void* d_out, int out_size)
{
    const float* x    = (const float*)d_in[0];
    const float* Wq   = (const float*)d_in[1];
    const float* Wk   = (const float*)d_in[2];
    const float* Wv   = (const float*)d_in[3];
    const float* Wout = (const float*)d_in[4];
    float* out = (float*)d_out;

    cudaFuncSetAttribute(flash_tc, cudaFuncAttributeMaxDynamicSharedMemorySize,
                         FLASH_SMEM);
    cudaFuncSetAttribute(gemm_qkv_tc, cudaFuncAttributeMaxDynamicSharedMemorySize,
                         GEMM_SMEM);
    cudaFuncSetAttribute(gemm_out_tc, cudaFuncAttributeMaxDynamicSharedMemorySize,
                         GEMM_SMEM);

    split_inputs<<<(XN4 + 4 * WN4) / 256, 256>>>(x, Wq, Wk, Wv, Wout);
    gemm_qkv_tc<<<dim3(CC / 128, MM / 128, 3), 256, GEMM_SMEM>>>();
    flash_tc<<<dim3(TT / 128, BB * HH), 128, FLASH_SMEM>>>();
    gemm_out_tc<<<dim3(CC / 128, MM / 128), 256, GEMM_SMEM>>>(out);
}

// round 16
// speedup vs baseline: 1.0250x; 1.0250x over previous
#include <cuda_runtime.h>
#include <cuda_bf16.h>
#include <math.h>
#include <stdint.h>

// Problem constants
#define BB 2
#define HH 8
#define TT 4096
#define DD 64
#define CC 512
#define MM (BB*TT)   // 8192

// Scratch (device globals: allocation-free)
__device__ float g_q[BB*HH*TT*DD];   // [b,h,t,d]  (tf32-rounded fp32)
__device__ float g_k[BB*HH*TT*DD];
__device__ float g_v[BB*HH*TT*DD];

// Pre-split bf16 hi/lo planes (stored as bf16x2 in uint32)
__device__ uint32_t g_xh[MM*CC/2], g_xl[MM*CC/2];       // x
__device__ uint32_t g_wh[4*CC*CC/2], g_wl[4*CC*CC/2];   // Wq,Wk,Wv,Wout
__device__ uint32_t g_yh[MM*CC/2], g_yl[MM*CC/2];       // attention output

// ---------------------------------------------------------------------------
// Helpers
// ---------------------------------------------------------------------------

__device__ __forceinline__ uint32_t f2tf(float f) {
    uint32_t u;
    asm("cvt.rna.tf32.f32 %0, %1;" : "=r"(u) : "f"(f));
    return u;
}
__device__ __forceinline__ float ex2(float x) {
    float y;
    asm("ex2.approx.ftz.f32 %0, %1;" : "=f"(y) : "f"(x));
    return y;
}
__device__ __forceinline__ void mma_tf32(float c[4],
                                         uint32_t a0, uint32_t a1, uint32_t a2, uint32_t a3,
                                         uint32_t b0, uint32_t b1) {
    asm volatile(
        "mma.sync.aligned.m16n8k8.row.col.f32.tf32.tf32.f32 "
        "{%0,%1,%2,%3}, {%4,%5,%6,%7}, {%8,%9}, {%0,%1,%2,%3};"
        : "+f"(c[0]), "+f"(c[1]), "+f"(c[2]), "+f"(c[3])
        : "r"(a0), "r"(a1), "r"(a2), "r"(a3), "r"(b0), "r"(b1));
}
__device__ __forceinline__ void mma_bf16(float c[4],
                                         uint32_t a0, uint32_t a1, uint32_t a2, uint32_t a3,
                                         uint32_t b0, uint32_t b1) {
    asm volatile(
        "mma.sync.aligned.m16n8k16.row.col.f32.bf16.bf16.f32 "
        "{%0,%1,%2,%3}, {%4,%5,%6,%7}, {%8,%9}, {%0,%1,%2,%3};"
        : "+f"(c[0]), "+f"(c[1]), "+f"(c[2]), "+f"(c[3])
        : "r"(a0), "r"(a1), "r"(a2), "r"(a3), "r"(b0), "r"(b1));
}

// bf16 hi/lo split of a float pair; hi+lo captures ~16 mantissa bits.
__device__ __forceinline__ void split2_bf16(float x, float y, uint32_t& hi, uint32_t& lo) {
    __nv_bfloat162 h = __floats2bfloat162_rn(x, y);
    float rx = x - __bfloat162float(h.x);
    float ry = y - __bfloat162float(h.y);
    __nv_bfloat162 l = __floats2bfloat162_rn(rx, ry);
    hi = *(uint32_t*)&h;
    lo = *(uint32_t*)&l;
}

__device__ __forceinline__ void cp16(uint32_t saddr, const void* gptr) {
    asm volatile("cp.async.cg.shared.global [%0], [%1], 16;"
                 :: "r"(saddr), "l"(gptr));
}
__device__ __forceinline__ void cp_commit() {
    asm volatile("cp.async.commit_group;");
}
__device__ __forceinline__ void cp_wait1() {
    asm volatile("cp.async.wait_group 1;");
}
__device__ __forceinline__ void cp_wait0() {
    asm volatile("cp.async.wait_group 0;");
}

// ---------------------------------------------------------------------------
// Pre-split: x and the four W matrices -> bf16 hi/lo planes in gmem.
// ---------------------------------------------------------------------------

#define XN4 (MM*CC/4)   // float4 count in x
#define WN4 (CC*CC/4)   // float4 count per W

__global__ __launch_bounds__(256) void split_inputs(const float* __restrict__ x,
                                                    const float* __restrict__ Wq,
                                                    const float* __restrict__ Wk,
                                                    const float* __restrict__ Wv,
                                                    const float* __restrict__ Wo)
{
    int i = blockIdx.x * 256 + threadIdx.x;
    const float* src;
    uint32_t *dh, *dl;
    int off;
    if (i < XN4) {
        src = x; dh = g_xh; dl = g_xl; off = i;
    } else {
        int j = i - XN4;
        int w = j / WN4;
        off = j - w * WN4;
        src = (w == 0) ? Wq : (w == 1) ? Wk : (w == 2) ? Wv : Wo;
        dh = g_wh + w * (CC * CC / 2);
        dl = g_wl + w * (CC * CC / 2);
    }
    float4 v = ((const float4*)src)[off];
    uint32_t h0, l0, h1, l1;
    split2_bf16(v.x, v.y, h0, l0);
    split2_bf16(v.z, v.w, h1, l1);
    ((uint2*)dh)[off] = make_uint2(h0, h1);
    ((uint2*)dl)[off] = make_uint2(l0, l1);
}

// ---------------------------------------------------------------------------
// Tensor-core split-bf16 GEMM, pre-split inputs, cp.async 2-stage (unchanged).
// ---------------------------------------------------------------------------

#define GSTR 20
#define GPLANE (128 * GSTR)                        // u32 per plane
#define GSTAGE4 (4 * GPLANE)                       // u32 per stage
#define GEMM_SMEM (2 * GSTAGE4 * (int)sizeof(uint32_t))   // 81920 B

__device__ __forceinline__ void g_issue(uint32_t sbase,
                                        const uint32_t* __restrict__ Ah_g,
                                        const uint32_t* __restrict__ Al_g,
                                        const uint32_t* __restrict__ Bh_g,
                                        const uint32_t* __restrict__ Bl_g,
                                        int k0u)   // u32 col offset = k0/2
{
    const int tid = threadIdx.x;
#pragma unroll
    for (int i = 0; i < 8; i++) {
        int c = i * 256 + tid;          // 0..2047
        int plane = c >> 9;             // 512 chunks per plane
        int row = (c >> 2) & 127;
        int ch  = c & 3;                // 16B chunk within row
        const uint32_t* g = (plane == 0) ? Ah_g : (plane == 1) ? Al_g
                          : (plane == 2) ? Bh_g : Bl_g;
        uint32_t dst = sbase + (plane * GPLANE + row * GSTR + ch * 4) * 4;
        cp16(dst, g + (size_t)row * (CC / 2) + k0u + ch * 4);
    }
}

__device__ __forceinline__ void gemm_mainloop(const uint32_t* __restrict__ Ah_g,
                                              const uint32_t* __restrict__ Al_g,
                                              const uint32_t* __restrict__ Bh_g,
                                              const uint32_t* __restrict__ Bl_g,
                                              uint32_t* smu,
                                              float acc[2][8][4])
{
    const int tid  = threadIdx.x;
    const int w    = tid >> 5;
    const int lane = tid & 31;
    const int g    = lane >> 2;
    const int t    = lane & 3;
    const int wm   = w >> 1;
    const int wn   = w & 1;

    const uint32_t sm_u32 = (uint32_t)__cvta_generic_to_shared(smu);

#pragma unroll
    for (int mt = 0; mt < 2; mt++)
#pragma unroll
        for (int nt = 0; nt < 8; nt++)
#pragma unroll
            for (int k = 0; k < 4; k++) acc[mt][nt][k] = 0.f;

    g_issue(sm_u32, Ah_g, Al_g, Bh_g, Bl_g, 0);
    cp_commit();

    const int NITER = CC / 32;          // 16
    for (int it = 0; it < NITER; it++) {
        if (it + 1 < NITER) {
            g_issue(sm_u32 + (((it + 1) & 1) * GSTAGE4) * 4,
                    Ah_g, Al_g, Bh_g, Bl_g, (it + 1) * 16);
            cp_commit();
            cp_wait1();
        } else {
            cp_wait0();
        }
        __syncthreads();

        const uint32_t* stage = smu + (it & 1) * GSTAGE4;
        const uint32_t* Ah = stage;
        const uint32_t* Al = stage + GPLANE;
        const uint32_t* Bh = stage + 2 * GPLANE;
        const uint32_t* Bl = stage + 3 * GPLANE;

#pragma unroll
        for (int ks = 0; ks < 2; ks++) {
            const int kb = ks * 8;
            uint32_t ah[2][4], al[2][4], b[8][2];
#pragma unroll
            for (int mt = 0; mt < 2; mt++) {
                int r = wm * 32 + mt * 16 + g;
                ah[mt][0] = Ah[(r)     * GSTR + kb + t];
                ah[mt][1] = Ah[(r + 8) * GSTR + kb + t];
                ah[mt][2] = Ah[(r)     * GSTR + kb + t + 4];
                ah[mt][3] = Ah[(r + 8) * GSTR + kb + t + 4];
                al[mt][0] = Al[(r)     * GSTR + kb + t];
                al[mt][1] = Al[(r + 8) * GSTR + kb + t];
                al[mt][2] = Al[(r)     * GSTR + kb + t + 4];
                al[mt][3] = Al[(r + 8) * GSTR + kb + t + 4];
            }
#pragma unroll
            for (int nt = 0; nt < 8; nt++) {
                int cn = wn * 64 + nt * 8 + g;
                b[nt][0] = Bh[cn * GSTR + kb + t];
                b[nt][1] = Bh[cn * GSTR + kb + t + 4];
            }
#pragma unroll
            for (int nt = 0; nt < 8; nt++)
#pragma unroll
                for (int mt = 0; mt < 2; mt++)
                    mma_bf16(acc[mt][nt], ah[mt][0], ah[mt][1], ah[mt][2], ah[mt][3],
                             b[nt][0], b[nt][1]);
#pragma unroll
            for (int nt = 0; nt < 8; nt++)
#pragma unroll
                for (int mt = 0; mt < 2; mt++)
                    mma_bf16(acc[mt][nt], al[mt][0], al[mt][1], al[mt][2], al[mt][3],
                             b[nt][0], b[nt][1]);
#pragma unroll
            for (int nt = 0; nt < 8; nt++) {
                int cn = wn * 64 + nt * 8 + g;
                b[nt][0] = Bl[cn * GSTR + kb + t];
                b[nt][1] = Bl[cn * GSTR + kb + t + 4];
            }
#pragma unroll
            for (int nt = 0; nt < 8; nt++)
#pragma unroll
                for (int mt = 0; mt < 2; mt++)
                    mma_bf16(acc[mt][nt], ah[mt][0], ah[mt][1], ah[mt][2], ah[mt][3],
                             b[nt][0], b[nt][1]);
        }
        __syncthreads();
    }
}

// QKV projections: epilogue rounds to tf32 and scatters into [b,h,t,d].
__global__ __launch_bounds__(256, 2) void gemm_qkv_tc()
{
    const int z = blockIdx.z;
    float* Out = (z == 0) ? g_q : (z == 1) ? g_k : g_v;

    extern __shared__ uint32_t smu[];
    const int m0 = blockIdx.y * 128, n0 = blockIdx.x * 128;

    float acc[2][8][4];
    gemm_mainloop(g_xh + (size_t)m0 * (CC / 2),
                  g_xl + (size_t)m0 * (CC / 2),
                  g_wh + (size_t)z * (CC * CC / 2) + (size_t)n0 * (CC / 2),
                  g_wl + (size_t)z * (CC * CC / 2) + (size_t)n0 * (CC / 2),
                  smu, acc);

    const int lane = threadIdx.x & 31;
    const int w    = threadIdx.x >> 5;
    const int g = lane >> 2, t = lane & 3;
    const int wm = w >> 1, wn = w & 1;

#pragma unroll
    for (int mt = 0; mt < 2; mt++) {
        int row = m0 + wm * 32 + mt * 16 + g;
        int b_  = row >> 12;
        int tr  = row & 4095;
#pragma unroll
        for (int nt = 0; nt < 8; nt++) {
            int col = n0 + wn * 64 + nt * 8 + 2 * t;
            int h = col >> 6, d = col & 63;
            float* base = Out + (((size_t)(b_ * HH + h) * TT) + tr) * DD + d;
            *(float2*)base = make_float2(__uint_as_float(f2tf(acc[mt][nt][0])),
                                         __uint_as_float(f2tf(acc[mt][nt][1])));
            *(float2*)(base + 8 * DD) =
                          make_float2(__uint_as_float(f2tf(acc[mt][nt][2])),
                                      __uint_as_float(f2tf(acc[mt][nt][3])));
        }
    }
}

// Output projection: A = pre-split y planes, B = Wout plane; fp32 epilogue.
__global__ __launch_bounds__(256, 2) void gemm_out_tc(float* __restrict__ OutP)
{
    extern __shared__ uint32_t smu[];
    const int m0 = blockIdx.y * 128, n0 = blockIdx.x * 128;

    float acc[2][8][4];
    gemm_mainloop(g_yh + (size_t)m0 * (CC / 2),
                  g_yl + (size_t)m0 * (CC / 2),
                  g_wh + 3 * (size_t)(CC * CC / 2) + (size_t)n0 * (CC / 2),
                  g_wl + 3 * (size_t)(CC * CC / 2) + (size_t)n0 * (CC / 2),
                  smu, acc);

    const int lane = threadIdx.x & 31;
    const int w    = threadIdx.x >> 5;
    const int g = lane >> 2, t = lane & 3;
    const int wm = w >> 1, wn = w & 1;

#pragma unroll
    for (int mt = 0; mt < 2; mt++) {
        int row = m0 + wm * 32 + mt * 16 + g;
#pragma unroll
        for (int nt = 0; nt < 8; nt++) {
            int col = n0 + wn * 64 + nt * 8 + 2 * t;
            float* base = OutP + (size_t)row * CC + col;
            *(float2*)base            = make_float2(acc[mt][nt][0], acc[mt][nt][1]);
            *(float2*)(base + 8 * CC) = make_float2(acc[mt][nt][2], acc[mt][nt][3]);
        }
    }
}

// ---------------------------------------------------------------------------
// Flash attention (tf32 mma m16n8k8), fixed-max softmax, register-P,
// DOUBLE-BUFFERED K/V. 4 warps, 128-query tile, 32 rows/warp (mt=2),
// 64-key tiles.
//  - P never touches smem: QK C-frags are shuffle-permuted into the PV
//    A-frag layout (validated R11), softmax runs on permuted values.
//  - K(jt+2)/V(jt+2) issued at END of iter jt into the alternate buffer:
//    2 barriers/iter (was 4), prefetch depth ~1.5 iterations.
//  - Smem: Q 34816 + 2xK 34816 + 2xV 36864 = 106496 B -> 2 CTAs/SM.
// ---------------------------------------------------------------------------

#define KSTR 68
#define VSTR 72
#define KBUF (64 * KSTR)
#define VBUF (64 * VSTR)
#define FLASH_SMEM ((128*KSTR + 2*KBUF + 2*VBUF) * (int)sizeof(uint32_t)) // 106496
#define MBIAS 16.0f

__global__ __launch_bounds__(128, 2) void flash_tc()
{
    const int bh    = blockIdx.y;
    const int qtile = gridDim.x - 1 - blockIdx.x;   // long tiles launch first
    const int q0    = qtile * 128;

    const float* Qg = g_q + (size_t)bh * TT * DD;
    const float* Kg = g_k + (size_t)bh * TT * DD;
    const float* Vg = g_v + (size_t)bh * TT * DD;

    extern __shared__ uint32_t smu[];
    uint32_t* Qs = smu;                     // 128 x KSTR
    uint32_t* Kb = Qs + 128 * KSTR;         // 2 x (64 x KSTR)
    uint32_t* Vb = Kb + 2 * KBUF;           // 2 x (64 x VSTR)
    const uint32_t Kb_s = (uint32_t)__cvta_generic_to_shared(Kb);
    const uint32_t Vb_s = (uint32_t)__cvta_generic_to_shared(Vb);

    const int tid  = threadIdx.x;
    const int w    = tid >> 5;              // warp 0..3 -> rows w*32..w*32+31
    const int lane = tid & 31;
    const int g    = lane >> 2;
    const int t    = lane & 3;

    const int ntiles = 2 * qtile + 2;

    // Issue K+V tile for stage s (= j0/64) into buffer s&1, as ONE group.
    auto issueKV = [&](int j0) {
        const uint32_t kb = Kb_s + ((j0 >> 6) & 1) * KBUF * 4;
        const uint32_t vb = Vb_s + ((j0 >> 6) & 1) * VBUF * 4;
#pragma unroll
        for (int i = 0; i < 8; i++) {
            int c = i * 128 + tid;
            int row = c >> 4, ch = c & 15;
            cp16(kb + (row * KSTR + ch * 4) * 4, Kg + (size_t)(j0 + row) * DD + ch * 4);
        }
#pragma unroll
        for (int i = 0; i < 8; i++) {
            int c = i * 128 + tid;
            int row = c >> 4, ch = c & 15;
            cp16(vb + (row * VSTR + ch * 4) * 4, Vg + (size_t)(j0 + row) * DD + ch * 4);
        }
    };

    // Prologue: stages 0 and 1 in flight (group order = stage order).
    issueKV(0); cp_commit();
    if (1 < ntiles) issueKV(64);
    cp_commit();

    // Q tile copy (no conversion: already tf32-valued fp32)
    for (int i = tid; i < 2048; i += 128) {
        int r = i >> 4, c4 = (i & 15) * 4;
        *(float4*)&Qs[r * KSTR + c4] = *(const float4*)(Qg + (size_t)(q0 + r) * DD + c4);
    }

    float l[4];                             // [mt*2 + half]
#pragma unroll
    for (int i = 0; i < 4; i++) l[i] = 0.f;
    float o[2][8][4];
#pragma unroll
    for (int mt = 0; mt < 2; mt++)
#pragma unroll
        for (int dt = 0; dt < 8; dt++)
#pragma unroll
            for (int k = 0; k < 4; k++) o[mt][dt][k] = 0.f;

    const float SC = 0.125f * 1.4426950408889634f;   // 1/sqrt(64) * log2(e)
    const int lsrc = (lane & 28) | (t >> 1);         // g*4 + (t>>1)
    const bool odd = (t & 1);
    const int rA0 = w * 32 + g;

    for (int jt = 0; jt < ntiles; jt++) {
        const int j0 = jt * 64;
        const uint32_t* Ks = Kb + (jt & 1) * KBUF;
        const uint32_t* Vs = Vb + (jt & 1) * VBUF;

        cp_wait1();            // stage jt complete (jt+1 still in flight)
        __syncthreads();       // K/V visible to all; Q staged (jt==0)

        // ---- S = Q K^T
        float c[2][8][4];
#pragma unroll
        for (int mt = 0; mt < 2; mt++)
#pragma unroll
            for (int nt = 0; nt < 8; nt++)
#pragma unroll
                for (int k = 0; k < 4; k++) c[mt][nt][k] = 0.f;

#pragma unroll
        for (int ks = 0; ks < 8; ks++) {
            uint32_t a[2][4];
#pragma unroll
            for (int mt = 0; mt < 2; mt++) {
                int r = rA0 + mt * 16;
                a[mt][0] = Qs[(r)     * KSTR + ks * 8 + t];
                a[mt][1] = Qs[(r + 8) * KSTR + ks * 8 + t];
                a[mt][2] = Qs[(r)     * KSTR + ks * 8 + t + 4];
                a[mt][3] = Qs[(r + 8) * KSTR + ks * 8 + t + 4];
            }
#pragma unroll
            for (int nt = 0; nt < 8; nt++) {
                uint32_t b0 = Ks[(nt * 8 + g) * KSTR + ks * 8 + t];
                uint32_t b1 = Ks[(nt * 8 + g) * KSTR + ks * 8 + t + 4];
#pragma unroll
                for (int mt = 0; mt < 2; mt++)
                    mma_tf32(c[mt][nt], a[mt][0], a[mt][1], a[mt][2], a[mt][3], b0, b1);
            }
        }

        // ---- register permute: C-frag {cols 2t,2t+1} -> A-frag {cols t,t+4}
        // After: c[mt][nt] = { S[qA][j], S[qA+8][j], S[qA][j+4], S[qA+8][j+4] },
        // j = j0 + nt*8 + t.
#pragma unroll
        for (int mt = 0; mt < 2; mt++)
#pragma unroll
            for (int nt = 0; nt < 8; nt++) {
                float c0 = c[mt][nt][0], c1 = c[mt][nt][1];
                float c2 = c[mt][nt][2], c3 = c[mt][nt][3];
                float x0 = __shfl_sync(0xffffffffu, c0, lsrc);
                float x1 = __shfl_sync(0xffffffffu, c1, lsrc);
                float y0 = __shfl_sync(0xffffffffu, c2, lsrc);
                float y1 = __shfl_sync(0xffffffffu, c3, lsrc);
                float z0 = __shfl_sync(0xffffffffu, c0, lsrc + 2);
                float z1 = __shfl_sync(0xffffffffu, c1, lsrc + 2);
                float u0 = __shfl_sync(0xffffffffu, c2, lsrc + 2);
                float u1 = __shfl_sync(0xffffffffu, c3, lsrc + 2);
                c[mt][nt][0] = odd ? x1 : x0;
                c[mt][nt][1] = odd ? y1 : y0;
                c[mt][nt][2] = odd ? z1 : z0;
                c[mt][nt][3] = odd ? u1 : u0;
            }

        // ---- fixed-max softmax on permuted values; mask -> p = 0
        const bool diag = (jt >= 2 * qtile);
#pragma unroll
        for (int mt = 0; mt < 2; mt++) {
            const int qA = q0 + rA0 + mt * 16;
            float lpA = 0.f, lpB = 0.f;
#pragma unroll
            for (int nt = 0; nt < 8; nt++) {
                int j = j0 + nt * 8 + t;
                float s0 = c[mt][nt][0] * SC - MBIAS;   // row qA,   col j
                float s1 = c[mt][nt][1] * SC - MBIAS;   // row qA+8, col j
                float s2 = c[mt][nt][2] * SC - MBIAS;   // row qA,   col j+4
                float s3 = c[mt][nt][3] * SC - MBIAS;   // row qA+8, col j+4
                if (diag) {
                    if (j     > qA)     s0 = -1e30f;
                    if (j     > qA + 8) s1 = -1e30f;
                    if (j + 4 > qA)     s2 = -1e30f;
                    if (j + 4 > qA + 8) s3 = -1e30f;
                }
                float p0 = ex2(s0), p1 = ex2(s1);
                float p2 = ex2(s2), p3 = ex2(s3);
                lpA += p0 + p2;  lpB += p1 + p3;
                c[mt][nt][0] = p0; c[mt][nt][1] = p1;
                c[mt][nt][2] = p2; c[mt][nt][3] = p3;
            }
            l[2 * mt]     += lpA;
            l[2 * mt + 1] += lpB;
        }

        // ---- O += P V  (P straight from registers)
#pragma unroll
        for (int kt = 0; kt < 8; kt++) {
            uint32_t a[2][4];
#pragma unroll
            for (int mt = 0; mt < 2; mt++) {
                a[mt][0] = f2tf(c[mt][kt][0]);
                a[mt][1] = f2tf(c[mt][kt][1]);
                a[mt][2] = f2tf(c[mt][kt][2]);
                a[mt][3] = f2tf(c[mt][kt][3]);
            }
#pragma unroll
            for (int dt = 0; dt < 8; dt++) {
                uint32_t b0 = Vs[(kt * 8 + t)     * VSTR + dt * 8 + g];
                uint32_t b1 = Vs[(kt * 8 + t + 4) * VSTR + dt * 8 + g];
#pragma unroll
                for (int mt = 0; mt < 2; mt++)
                    mma_tf32(o[mt][dt], a[mt][0], a[mt][1], a[mt][2], a[mt][3], b0, b1);
            }
        }

        // ---- all warps done with buffer jt&1 -> refill it with stage jt+2
        __syncthreads();
        if (jt + 2 < ntiles) issueKV(j0 + 128);
        cp_commit();           // always commit to keep group accounting aligned
    }

    // ---- normalize + write y as pre-split bf16 hi/lo planes
    const int h  = bh & 7;
    const int b_ = bh >> 3;
#pragma unroll
    for (int mt = 0; mt < 2; mt++) {
        float lA = l[2 * mt];
        lA += __shfl_xor_sync(0xffffffffu, lA, 1);
        lA += __shfl_xor_sync(0xffffffffu, lA, 2);
        float lB = l[2 * mt + 1];
        lB += __shfl_xor_sync(0xffffffffu, lB, 1);
        lB += __shfl_xor_sync(0xffffffffu, lB, 2);
        const float iA = 1.f / lA, iB = 1.f / lB;

        const int qA = q0 + rA0 + mt * 16;
        size_t baseA = ((size_t)(b_ * TT + qA))     * CC + h * 64;
        size_t baseB = ((size_t)(b_ * TT + qA + 8)) * CC + h * 64;
#pragma unroll
        for (int dt = 0; dt < 8; dt++) {
            uint32_t hh, ll;
            split2_bf16(o[mt][dt][0] * iA, o[mt][dt][1] * iA, hh, ll);
            size_t ia = (baseA + dt * 8 + 2 * t) >> 1;
            g_yh[ia] = hh; g_yl[ia] = ll;
            split2_bf16(o[mt][dt][2] * iB, o[mt][dt][3] * iB, hh, ll);
            size_t ib = (baseB + dt * 8 + 2 * t) >> 1;
            g_yh[ib] = hh; g_yl[ib] = ll;
        }
    }
}

// ---------------------------------------------------------------------------

extern "C" void kernel_launch(void* const* d_in, const int* in_sizes, int n_in,
                              void* d_out, int out_size)
{
    const float* x    = (const float*)d_in[0];
    const float* Wq   = (const float*)d_in[1];
    const float* Wk   = (const float*)d_in[2];
    const float* Wv   = (const float*)d_in[3];
    const float* Wout = (const float*)d_in[4];
    float* out = (float*)d_out;

    cudaFuncSetAttribute(flash_tc, cudaFuncAttributeMaxDynamicSharedMemorySize,
                         FLASH_SMEM);
    cudaFuncSetAttribute(gemm_qkv_tc, cudaFuncAttributeMaxDynamicSharedMemorySize,
                         GEMM_SMEM);
    cudaFuncSetAttribute(gemm_out_tc, cudaFuncAttributeMaxDynamicSharedMemorySize,
                         GEMM_SMEM);

    split_inputs<<<(XN4 + 4 * WN4) / 256, 256>>>(x, Wq, Wk, Wv, Wout);
    gemm_qkv_tc<<<dim3(CC / 128, MM / 128, 3), 256, GEMM_SMEM>>>();
    flash_tc<<<dim3(TT / 128, BB * HH), 128, FLASH_SMEM>>>();
    gemm_out_tc<<<dim3(CC / 128, MM / 128), 256, GEMM_SMEM>>>(out);
}